// round 2
// baseline (speedup 1.0000x reference)
#include <cuda_runtime.h>
#include <cstdint>

// Problem constants
#define NSESS    4096
#define NTRIALS  2048
#define C_CHUNK  128                   // trials per output chunk
#define N_CHUNK  (NTRIALS / C_CHUNK)   // 16
#define WARMUP   48                    // warmup trials (contraction 0.8^48 -> ~1e-4 err)
#define TILE     16                    // trials per smem tile

// smem layout per warp (one warp per block)
#define ROW_BYTES   (TILE * 12)          // 192 B input per session per tile
#define ROW_CHUNKS  (ROW_BYTES / 16)     // 12 x 16B cp.async chunks per row
#define ROW_STRIDE  208                  // 13*16: conflict-free LDS.128 quarter-warp phases
#define IN_TILE_BYTES  (32 * ROW_STRIDE) // 6656 B per stage
#define OUT_ROW_F2  17                   // out staging row stride in float2
#define OUT_TILE_BYTES (32 * OUT_ROW_F2 * 8)  // 4352 B
#define SMEM_BYTES  (2 * IN_TILE_BYTES + OUT_TILE_BYTES)  // 17664 B

__device__ __forceinline__ void cp_async16(uint32_t dst, const void* src) {
    asm volatile("cp.async.cg.shared.global [%0], [%1], 16;\n"
                 :: "r"(dst), "l"(src));
}
__device__ __forceinline__ void cp_commit() {
    asm volatile("cp.async.commit_group;\n" ::: "memory");
}
__device__ __forceinline__ void cp_wait1() {
    asm volatile("cp.async.wait_group 1;\n" ::: "memory");
}
__device__ __forceinline__ void cp_wait0() {
    asm volatile("cp.async.wait_group 0;\n" ::: "memory");
}

// Stage one 32-session x TILE-trial tile into smem.
__device__ __forceinline__ void issue_tile(const char* __restrict__ src0,
                                           uint32_t sdst, int lane) {
#pragma unroll
    for (int m = 0; m < 12; m++) {
        int g   = lane + 32 * m;          // 0..383
        int row = g / ROW_CHUNKS;         // session within warp
        int cc  = g - row * ROW_CHUNKS;   // 16B chunk within row
        cp_async16(sdst + row * ROW_STRIDE + cc * 16,
                   src0 + (long)row * (NTRIALS * 12) + cc * 16);
    }
    cp_commit();
}

__global__ void __launch_bounds__(32)
hmm_filter_kernel(const float* __restrict__ in,
                  const float* __restrict__ p_stay_raw,
                  const float* __restrict__ c_raw,
                  float* __restrict__ out) {
    extern __shared__ char smem[];
    const int lane = threadIdx.x & 31;

    const int chunk = blockIdx.x & (N_CHUNK - 1);
    const int sess0 = (blockIdx.x >> 4) * 32;

    // model parameters
    const float p  = 1.0f / (1.0f + __expf(-p_stay_raw[0]));
    const float c  = 1.0f / (1.0f + __expf(-c_raw[0]));
    const float AmB = c;                  // A - B
    const float Bc  = 0.5f * (1.0f - c);  // B
    const float q  = 0.5f * (1.0f + p);
    const float qm = 0.5f * (1.0f - p);

    const int t_out0     = chunk * C_CHUNK;
    const int t_start    = (chunk == 0) ? 0 : (t_out0 - WARMUP);
    const int ntiles     = (t_out0 + C_CHUNK - t_start) / TILE;   // 8 or 11
    const int warm_tiles = (t_out0 - t_start) / TILE;             // 0 or 3

    char*   in_buf   = smem;
    float2* out_buf2 = (float2*)(smem + 2 * IN_TILE_BYTES);
    const uint32_t smem_in = (uint32_t)__cvta_generic_to_shared(in_buf);

    const char* gsrc = (const char*)in + ((long)sess0 * NTRIALS + t_start) * 12;

    // prologue
    issue_tile(gsrc, smem_in, lane);

    float v0 = 0.5f, v1 = 0.5f;

    for (int t = 0; t < ntiles; t++) {
        if (t + 1 < ntiles) {
            issue_tile(gsrc + (long)(t + 1) * (TILE * 12),
                       smem_in + ((t + 1) & 1) * IN_TILE_BYTES, lane);
            cp_wait1();
        } else {
            cp_wait0();
        }
        __syncwarp();

        const float4* rp =
            (const float4*)(in_buf + (t & 1) * IN_TILE_BYTES + lane * ROW_STRIDE);
        const bool do_out = (t >= warm_tiles);
        float2* ob = out_buf2 + lane * OUT_ROW_F2;

        float r_mid = 1.0f;

        // one HMM step; chain = mul(4)+fma(4) = 8 cyc
        #define STEP(CL, CR, O, I)                                          \
        {                                                                   \
            float _w0 = fmaf((CL), (O), (CR) * (1.0f - (O)));               \
            float _e0 = fmaf(_w0, AmB, Bc);                                 \
            float _e1 = 1.0f - _e0;                                         \
            float _k00 = q  * _e0, _k01 = qm * _e1;                         \
            float _k10 = qm * _e0, _k11 = q  * _e1;                         \
            float _a = fmaf(_k00, v0, _k01 * v1);                           \
            float _b = fmaf(_k10, v0, _k11 * v1);                           \
            float _r = __frcp_rn(_a + _b);                                  \
            if (do_out) ob[(I)] = make_float2(_a * _r, _b * _r);            \
            if ((I) == 7) r_mid = _r;                                       \
            v0 = _a; v1 = _b;                                               \
        }

#pragma unroll
        for (int g = 0; g < 4; g++) {
            float4 x0 = rp[3 * g + 0];   // cl0 cr0 o0  cl1
            float4 x1 = rp[3 * g + 1];   // cr1 o1  cl2 cr2
            float4 x2 = rp[3 * g + 2];   // o2  cl3 cr3 o3
            STEP(x0.x, x0.y, x0.z, 4 * g + 0);
            STEP(x0.w, x1.x, x1.y, 4 * g + 1);
            STEP(x1.z, x1.w, x2.x, 4 * g + 2);
            STEP(x2.y, x2.z, x2.w, 4 * g + 3);
        }
        #undef STEP

        // periodic renorm with mid-tile reciprocal (rcp latency off the chain tail)
        v0 *= r_mid;
        v1 *= r_mid;

        if (do_out) {
            __syncwarp();
            const long tout = (long)t_start + (long)t * TILE;
            float2* og = (float2*)out + (long)sess0 * NTRIALS + tout;
            // 32 sessions x 16 float2, two rows per warp instruction
#pragma unroll
            for (int j = 0; j < 16; j++) {
                int row = j * 2 + (lane >> 4);
                int col = lane & 15;
                og[(long)row * NTRIALS + col] = out_buf2[row * OUT_ROW_F2 + col];
            }
            __syncwarp();
        }
    }
}

extern "C" void kernel_launch(void* const* d_in, const int* in_sizes, int n_in,
                              void* d_out, int out_size) {
    const float* in   = (const float*)d_in[0];
    const float* praw = (const float*)d_in[1];
    const float* craw = (const float*)d_in[2];
    float* out = (float*)d_out;

    const int grid = (NSESS / 32) * N_CHUNK;   // 2048 blocks, 1 warp each
    hmm_filter_kernel<<<grid, 32, SMEM_BYTES>>>(in, praw, craw, out);
}

// round 3
// speedup vs baseline: 1.0980x; 1.0980x over previous
#include <cuda_runtime.h>
#include <cstdint>

#define NSESS    4096
#define NTRIALS  2048
#define NWORDS   (NTRIALS / 32)        // 64 packed words per session

// filter chunking
#define FCHUNK   64                    // output trials per warp
#define FNCHUNK  (NTRIALS / FCHUNK)    // 32 chunks
#define FWARM    64                    // warmup trials (0.8^64 ~ 6e-7 contraction)

// packed bits scratch: bit i of packed[w*NSESS+s] = (chose_left==outcome) at trial w*32+i
__device__ uint32_t g_packed[NWORDS * NSESS];

// ---------------------------------------------------------------------------
// Kernel 1: pack. One warp per session; 16 iters x 128 trials (1536 B) each.
// Lane l handles trials 4l..4l+3 of the iter via 3 float4 loads (48 B).
// ---------------------------------------------------------------------------
__global__ void __launch_bounds__(128)
pack_kernel(const float* __restrict__ in, uint32_t* __restrict__ packed) {
    const int lane = threadIdx.x & 31;
    const int s    = blockIdx.x * 4 + (threadIdx.x >> 5);   // session

    const float* srow = in + (long)s * (NTRIALS * 3);

#pragma unroll 4
    for (int it = 0; it < 16; it++) {
        const float4* p = (const float4*)(srow + it * 384) + 3 * lane;
        float4 x0 = p[0];   // cl0 cr0 o0  cl1
        float4 x1 = p[1];   // cr1 o1  cl2 cr2
        float4 x2 = p[2];   // o2  cl3 cr3 o3

        int b0 = (x0.x == x0.z);
        int b1 = (x0.w == x1.y);
        int b2 = (x1.z == x2.x);
        int b3 = (x2.y == x2.w);
        uint32_t nib = (uint32_t)(b0 | (b1 << 1) | (b2 << 2) | (b3 << 3));
        uint32_t v = nib << ((lane & 7) * 4);
        v |= __shfl_xor_sync(0xFFFFFFFFu, v, 1);
        v |= __shfl_xor_sync(0xFFFFFFFFu, v, 2);
        v |= __shfl_xor_sync(0xFFFFFFFFu, v, 4);
        // lanes 0,8,16,24 hold words it*4 + 0..3
        if ((lane & 7) == 0) {
            int w = it * 4 + (lane >> 3);
            packed[w * NSESS + s] = v;
        }
    }
}

// ---------------------------------------------------------------------------
// Kernel 2: filter. One warp = 32 sessions x one 64-trial chunk (+64 warmup).
// Coefficients selected per-bit from 4 constants; chain = mul+fma = 8 cyc/step.
// Outputs staged in smem, flushed as coalesced 256 B stores.
// ---------------------------------------------------------------------------
#define OUT_ROW_F2 17                       // smem staging row stride (float2)
#define WARP_SMEM  (32 * OUT_ROW_F2)        // float2 per warp

__global__ void __launch_bounds__(128)
filter_kernel(const uint32_t* __restrict__ packed,
              const float* __restrict__ p_stay_raw,
              const float* __restrict__ c_raw,
              float* __restrict__ out) {
    __shared__ float2 stage[4 * WARP_SMEM];

    const int lane  = threadIdx.x & 31;
    const int wid   = threadIdx.x >> 5;
    const int gwarp = blockIdx.x * 4 + wid;
    const int chunk = gwarp & (FNCHUNK - 1);
    const int sess0 = (gwarp >> 5) * 32;    // FNCHUNK == 32

    // model constants
    const float p  = 1.0f / (1.0f + __expf(-p_stay_raw[0]));
    const float c  = 1.0f / (1.0f + __expf(-c_raw[0]));
    const float A  = 0.5f * (1.0f + c);
    const float B  = 0.5f * (1.0f - c);
    const float q  = 0.5f * (1.0f + p);
    const float qm = 0.5f * (1.0f - p);
    // bit=1 -> e=(A,B); bit=0 -> e=(B,A)
    const float k00_1 = q  * A, k00_0 = q  * B;
    const float k01_1 = qm * B, k01_0 = qm * A;
    const float k10_1 = qm * A, k10_0 = qm * B;
    const float k11_1 = q  * B, k11_0 = q  * A;

    const int t_out0     = chunk * FCHUNK;
    const int t_start    = (chunk == 0) ? 0 : (t_out0 - FWARM);
    const int w_start    = t_start >> 5;
    const int warm_words = (t_out0 - t_start) >> 5;   // 0 or 2
    const int nwords     = warm_words + (FCHUNK >> 5); // 2 or 4

    // fetch packed words (coalesced, mostly L2-resident)
    uint32_t wv[4];
#pragma unroll
    for (int k = 0; k < 4; k++)
        wv[k] = (k < nwords) ? packed[(w_start + k) * NSESS + sess0 + lane] : 0u;

    float2* ob = stage + wid * WARP_SMEM + lane * OUT_ROW_F2;
    float2* warp_stage = stage + wid * WARP_SMEM;

    float v0 = 0.5f, v1 = 0.5f;

    for (int k = 0; k < nwords; k++) {
        const uint32_t w = wv[k];
        if (k < warm_words) {
            // warmup: no outputs, renorm once per word
#pragma unroll
            for (int i = 0; i < 32; i++) {
                const bool bit = (w >> i) & 1u;
                float K00 = bit ? k00_1 : k00_0;
                float K01 = bit ? k01_1 : k01_0;
                float K10 = bit ? k10_1 : k10_0;
                float K11 = bit ? k11_1 : k11_0;
                float m0 = K01 * v1;
                float m1 = K10 * v0;
                float a = fmaf(K00, v0, m0);
                float b = fmaf(K11, v1, m1);
                v0 = a; v1 = b;
            }
            float r = __frcp_rn(v0 + v1);
            v0 *= r; v1 *= r;
        } else {
            // output word: two 16-step halves, each staged + flushed
#pragma unroll
            for (int h = 0; h < 2; h++) {
                float r_mid = 1.0f;
#pragma unroll
                for (int i = 0; i < 16; i++) {
                    const bool bit = (w >> (h * 16 + i)) & 1u;
                    float K00 = bit ? k00_1 : k00_0;
                    float K01 = bit ? k01_1 : k01_0;
                    float K10 = bit ? k10_1 : k10_0;
                    float K11 = bit ? k11_1 : k11_0;
                    float m0 = K01 * v1;
                    float m1 = K10 * v0;
                    float a = fmaf(K00, v0, m0);
                    float b = fmaf(K11, v1, m1);
                    float r = __frcp_rn(a + b);
                    ob[i] = make_float2(a * r, b * r);
                    if (i == 7) r_mid = r;
                    v0 = a; v1 = b;
                }
                v0 *= r_mid; v1 *= r_mid;   // keep magnitudes bounded

                __syncwarp();
                const int t = t_start + k * 32 + h * 16;
                float2* og = (float2*)out + (long)sess0 * NTRIALS + t;
#pragma unroll
                for (int j = 0; j < 16; j++) {
                    int row = 2 * j + (lane >> 4);
                    int col = lane & 15;
                    og[(long)row * NTRIALS + col] =
                        warp_stage[row * OUT_ROW_F2 + col];
                }
                __syncwarp();
            }
        }
    }
}

extern "C" void kernel_launch(void* const* d_in, const int* in_sizes, int n_in,
                              void* d_out, int out_size) {
    const float* in   = (const float*)d_in[0];
    const float* praw = (const float*)d_in[1];
    const float* craw = (const float*)d_in[2];
    float* out = (float*)d_out;

    uint32_t* packed = nullptr;
    cudaGetSymbolAddress((void**)&packed, g_packed);

    pack_kernel<<<NSESS / 4, 128>>>(in, packed);
    filter_kernel<<<(NSESS / 32) * FNCHUNK / 4, 128>>>(packed, praw, craw, out);
}